// round 8
// baseline (speedup 1.0000x reference)
#include <cuda_runtime.h>
#include <cstdint>
#include <float.h>

// Problem shape (fixed by the dataset): P=512, R=256, S=256
#define RR 256
#define SS 256
#define MAXP 512

// ---- static scratch (written every launch; idx only read when flag set) ----
__device__ float  g_row_thr[MAXP * RR];
__device__ float  g_col_thr[MAXP * SS];
__device__ int    g_row_idx[MAXP * RR * 3];
__device__ int    g_col_idx[MAXP * SS * 3];
__device__ int8_t g_row_flag[MAXP * RR];
__device__ int8_t g_col_flag[MAXP * SS];

// Predicate-free top-4 value tracker: 7 FMNMX, no SELs.
__device__ __forceinline__ void top4(float v, float& a, float& b, float& c, float& d) {
    float t1 = fminf(a, v);  a = fmaxf(a, v);
    float t2 = fminf(b, t1); b = fmaxf(b, t1);
    float t3 = fminf(c, t2); c = fmaxf(c, t2);
    d = fmaxf(d, t3);
}

// Stable top-3 insert with index (slow path only): strict '>' + increasing
// scan order reproduces jax.lax.top_k tie-breaking exactly.
__device__ __forceinline__ void ins3i(float v, int i,
                                      float& a, int& ia,
                                      float& b, int& ib,
                                      float& c, int& ic) {
    bool ga = v > a, gb = v > b, gc = v > c;
    c  = gb ? b  : (gc ? v : c);
    ic = gb ? ib : (gc ? i : ic);
    b  = ga ? a  : (gb ? v : b);
    ib = ga ? ia : (gb ? i : ib);
    a  = ga ? v : a;
    ia = ga ? i : ia;
}

// ================= K1: per-line thresholds (+ rare exact indices) ==========
__global__ __launch_bounds__(256)
void k1_thresholds(const float* __restrict__ score)
{
    __shared__ float tile[8][32][33];
    const int p = blockIdx.x;
    const int t = threadIdx.x;
    const int w = t >> 5;
    const int l = t & 31;
    const float* base = score + (size_t)p * (RR * SS);

    // ---- Phase 1: column top-4 values (thread t = column t; coalesced).
    // Two independent chains (row halves) for ILP, merged at the end.
    {
        float a1=-FLT_MAX,b1=-FLT_MAX,c1=-FLT_MAX,d1=-FLT_MAX;
        float a2=-FLT_MAX,b2=-FLT_MAX,c2=-FLT_MAX,d2=-FLT_MAX;
        #pragma unroll 4
        for (int r = 0; r < RR/2; r++) {
            top4(base[r * SS + t],            a1,b1,c1,d1);
            top4(base[(r + RR/2) * SS + t],   a2,b2,c2,d2);
        }
        top4(a2, a1,b1,c1,d1); top4(b2, a1,b1,c1,d1);
        top4(c2, a1,b1,c1,d1); top4(d2, a1,b1,c1,d1);

        const int gi = p * SS + t;
        const bool flag = (c1 == d1);           // boundary tie -> need indices
        g_col_thr[gi]  = c1;
        g_col_flag[gi] = flag ? 1 : 0;
        if (flag) {                              // rare exact path
            float A=-FLT_MAX,B=-FLT_MAX,C=-FLT_MAX; int ia=-1,ib=-1,ic=-1;
            for (int r = 0; r < RR; r++)
                ins3i(base[r * SS + t], r, A, ia, B, ib, C, ic);
            g_col_idx[gi*3+0] = ia; g_col_idx[gi*3+1] = ib; g_col_idx[gi*3+2] = ic;
        }
    }

    // ---- Phase 2: row top-4 via per-warp 32x32 SMEM transpose ----
    {
        float a1=-FLT_MAX,b1=-FLT_MAX,c1=-FLT_MAX,d1=-FLT_MAX;
        float a2=-FLT_MAX,b2=-FLT_MAX,c2=-FLT_MAX,d2=-FLT_MAX;
        const int row = w * 32 + l;
        for (int cb = 0; cb < 8; cb++) {
            #pragma unroll
            for (int j = 0; j < 32; j++)
                tile[w][j][l] = base[(w * 32 + j) * SS + cb * 32 + l];
            __syncwarp();
            if (cb < 4) {
                #pragma unroll
                for (int j = 0; j < 32; j++) top4(tile[w][l][j], a1,b1,c1,d1);
            } else {
                #pragma unroll
                for (int j = 0; j < 32; j++) top4(tile[w][l][j], a2,b2,c2,d2);
            }
            __syncwarp();
        }
        top4(a2, a1,b1,c1,d1); top4(b2, a1,b1,c1,d1);
        top4(c2, a1,b1,c1,d1); top4(d2, a1,b1,c1,d1);

        const int gi = p * RR + row;
        const bool flag = (c1 == d1);
        g_row_thr[gi]  = c1;
        g_row_flag[gi] = flag ? 1 : 0;
        if (flag) {
            float A=-FLT_MAX,B=-FLT_MAX,C=-FLT_MAX; int ia=-1,ib=-1,ic=-1;
            for (int s = 0; s < SS; s++)
                ins3i(base[row * SS + s], s, A, ia, B, ib, C, ic);
            g_row_idx[gi*3+0] = ia; g_row_idx[gi*3+1] = ib; g_row_idx[gi*3+2] = ic;
        }
    }
}

// ================= K2: streaming elementwise output ========================
// grid = P * 8 blocks; block b handles slice p = b>>3, rows [32*(b&7), +32)
__global__ __launch_bounds__(256)
void k2_emit(const float* __restrict__ score,
             const int* __restrict__ refm,
             const int* __restrict__ srcm,
             float* __restrict__ out,
             long long n_total)
{
    __shared__ float rthr_sh[32];
    __shared__ int   rflag_sh[32];
    __shared__ int   rmask_sh[32];
    __shared__ int   ridx_sh[32][3];

    const int b = blockIdx.x;
    const int p = b >> 3;
    const int panel = b & 7;
    const int t = threadIdx.x;

    if (t < 32) {
        const int rg = panel * 32 + t;
        const int gi = p * RR + rg;
        rthr_sh[t]  = g_row_thr[gi];
        const int f = g_row_flag[gi];
        rflag_sh[t] = f;
        rmask_sh[t] = refm[p * RR + rg];
        if (f) {
            ridx_sh[t][0] = g_row_idx[gi*3+0];
            ridx_sh[t][1] = g_row_idx[gi*3+1];
            ridx_sh[t][2] = g_row_idx[gi*3+2];
        }
    }
    __syncthreads();

    const int cg = t & 63;            // 4-column group
    const int r0 = t >> 6;            // warp-uniform row phase
    const int s0 = cg * 4;

    const float4 cthr = *reinterpret_cast<const float4*>(&g_col_thr[p * SS + s0]);
    const uint32_t cflags =
        (uint32_t)(g_col_flag[p*SS+s0+0] != 0)
      | ((uint32_t)(g_col_flag[p*SS+s0+1] != 0) << 1)
      | ((uint32_t)(g_col_flag[p*SS+s0+2] != 0) << 2)
      | ((uint32_t)(g_col_flag[p*SS+s0+3] != 0) << 3);
    const int4 sm4 = *reinterpret_cast<const int4*>(&srcm[p * SS + s0]);
    const bool sm0 = sm4.x != 0, sm1 = sm4.y != 0, sm2 = sm4.z != 0, sm3 = sm4.w != 0;

    int ci[4][3];
    if (cflags) {
        #pragma unroll
        for (int k = 0; k < 4; k++) {
            if ((cflags >> k) & 1) {
                const int gi = (p * SS + s0 + k) * 3;
                ci[k][0] = g_col_idx[gi+0]; ci[k][1] = g_col_idx[gi+1]; ci[k][2] = g_col_idx[gi+2];
            } else { ci[k][0] = ci[k][1] = ci[k][2] = -9; }
        }
    }

    const size_t slice = (size_t)p * (RR * SS) + (size_t)panel * 32 * SS;
    const float* basei = score + slice;
    float* outs = out + slice;
    float* outc = out + (size_t)n_total + slice;

    #pragma unroll
    for (int j = 0; j < 8; j++) {
        const int rl = j * 4 + r0;               // local row 0..31 (warp-uniform)
        const int rg = panel * 32 + rl;          // global row
        const float rthr = rthr_sh[rl];
        const bool  rm   = rmask_sh[rl] != 0;
        const size_t off = (size_t)rl * SS + s0;
        const float4 v4 = *reinterpret_cast<const float4*>(basei + off);

        bool fr0, fr1, fr2, fr3;
        if (!rflag_sh[rl]) {                     // warp-uniform branch
            fr0 = v4.x >= rthr; fr1 = v4.y >= rthr;
            fr2 = v4.z >= rthr; fr3 = v4.w >= rthr;
        } else {
            const int i0 = ridx_sh[rl][0], i1 = ridx_sh[rl][1], i2 = ridx_sh[rl][2];
            fr0 = (s0+0==i0)|(s0+0==i1)|(s0+0==i2);
            fr1 = (s0+1==i0)|(s0+1==i1)|(s0+1==i2);
            fr2 = (s0+2==i0)|(s0+2==i1)|(s0+2==i2);
            fr3 = (s0+3==i0)|(s0+3==i1)|(s0+3==i2);
        }

        bool fc0 = v4.x >= cthr.x, fc1 = v4.y >= cthr.y,
             fc2 = v4.z >= cthr.z, fc3 = v4.w >= cthr.w;
        if (cflags) {                            // rare (≈3 cols in 262144)
            if (cflags & 1) fc0 = (rg==ci[0][0])|(rg==ci[0][1])|(rg==ci[0][2]);
            if (cflags & 2) fc1 = (rg==ci[1][0])|(rg==ci[1][1])|(rg==ci[1][2]);
            if (cflags & 4) fc2 = (rg==ci[2][0])|(rg==ci[2][1])|(rg==ci[2][2]);
            if (cflags & 8) fc3 = (rg==ci[3][0])|(rg==ci[3][1])|(rg==ci[3][2]);
        }

        float4 so, co;
        {
            float e;
            e = __expf(v4.x); so.x = 0.5f*((fr0?e:0.f)+(fc0?e:0.f)); co.x = ((fr0|fc0)&&rm&&sm0)?1.f:0.f;
            e = __expf(v4.y); so.y = 0.5f*((fr1?e:0.f)+(fc1?e:0.f)); co.y = ((fr1|fc1)&&rm&&sm1)?1.f:0.f;
            e = __expf(v4.z); so.z = 0.5f*((fr2?e:0.f)+(fc2?e:0.f)); co.z = ((fr2|fc2)&&rm&&sm2)?1.f:0.f;
            e = __expf(v4.w); so.w = 0.5f*((fr3?e:0.f)+(fc3?e:0.f)); co.w = ((fr3|fc3)&&rm&&sm3)?1.f:0.f;
        }

        *reinterpret_cast<float4*>(outs + off) = so;
        *reinterpret_cast<float4*>(outc + off) = co;
    }
}

extern "C" void kernel_launch(void* const* d_in, const int* in_sizes, int n_in,
                              void* d_out, int out_size) {
    const float* score = (const float*)d_in[0];
    // d_in[1] = node_corr_scores (unused: conditional=False in reference)
    const int*   refm  = (const int*)d_in[2];   // bool -> int32 in harness
    const int*   srcm  = (const int*)d_in[3];
    float* out = (float*)d_out;

    const long long n_total = (long long)in_sizes[0];   // P*R*S
    const int P = (int)(n_total / (RR * SS));

    k1_thresholds<<<P, 256>>>(score);
    k2_emit<<<P * 8, 256>>>(score, refm, srcm, out, n_total);
}

// round 11
// speedup vs baseline: 1.0450x; 1.0450x over previous
#include <cuda_runtime.h>
#include <cstdint>
#include <float.h>

// Problem shape (fixed by the dataset): P=512, R=256, S=256
#define RR 256
#define SS 256
#define PSTRIDE 260   // panel row stride in floats: 16B-aligned, conflict-free both ways

// Predicate-free top-4 value tracker: 7 FMNMX.
__device__ __forceinline__ void top4(float v, float& a, float& b, float& c, float& d) {
    float t1 = fminf(a, v);  a = fmaxf(a, v);
    float t2 = fminf(b, t1); b = fmaxf(b, t1);
    float t3 = fminf(c, t2); c = fmaxf(c, t2);
    d = fmaxf(d, t3);
}

// Stable top-3 insert with index (rare tie path): strict '>' + increasing scan
// order reproduces jax.lax.top_k tie-breaking exactly.
__device__ __forceinline__ void ins3i(float v, int i,
                                      float& a, int& ia,
                                      float& b, int& ib,
                                      float& c, int& ic) {
    bool ga = v > a, gb = v > b, gc = v > c;
    c  = gb ? b  : (gc ? v : c);
    ic = gb ? ib : (gc ? i : ic);
    b  = ga ? a  : (gb ? v : b);
    ib = ga ? ia : (gb ? i : ib);
    a  = ga ? v : a;
    ia = ga ? i : ia;
}

__global__ __launch_bounds__(256, 4)
void iapm_fused(const float* __restrict__ score,
                const int* __restrict__ refm,
                const int* __restrict__ srcm,
                float* __restrict__ out,
                long long n_total)
{
    __shared__ float   panel[32 * PSTRIDE];    // 33,280 B ; reused as col-merge scratch
    __shared__ float   rpart[8][32][4];        //  4,096 B : per-warp row partials
    __shared__ float   rthr[RR], cthr[SS];     //  2,048 B
    __shared__ uint8_t rflag[RR], cflag[SS];   //    512 B
    __shared__ int     ridx[RR][3], cidx[SS][3];// 6,144 B
    __shared__ int     rmask_sh[RR];           //  1,024 B   (total ~47.1 KB)

    const int p  = blockIdx.x;
    const int t  = threadIdx.x;            // 0..255
    const int w  = t >> 5;                 // warp 0..7
    const int l  = t & 31;                 // lane
    const int g  = t >> 6;                 // row-phase group 0..3
    const int c4 = (t & 63) * 4;           // this thread's 4 fixed columns
    const float* base = score + (size_t)p * (RR * SS);

    rmask_sh[t] = refm[p * RR + t];

    // column top-4 accumulators (cols c4..c4+3), over rows g+4k (all panels)
    float4 ca, cb, cc, cd;
    ca = cb = cc = cd = make_float4(-FLT_MAX, -FLT_MAX, -FLT_MAX, -FLT_MAX);

    // ======================= PASS A: thresholds ============================
    for (int q = 0; q < 8; q++) {
        // async-load panel rows [32q, 32q+32) : 8 x 16B per thread
        #pragma unroll
        for (int k = 0; k < 8; k++) {
            const int r = g + 4 * k;
            uint32_t sa = (uint32_t)__cvta_generic_to_shared(&panel[r * PSTRIDE + c4]);
            const float* ga = base + (size_t)(32 * q + r) * SS + c4;
            asm volatile("cp.async.cg.shared.global [%0], [%1], 16;" :: "r"(sa), "l"(ga));
        }
        asm volatile("cp.async.commit_group;");
        asm volatile("cp.async.wait_group 0;" ::: "memory");
        __syncthreads();

        // ---- column update: my 4 columns over the 8 rows I loaded ----
        #pragma unroll
        for (int k = 0; k < 8; k++) {
            const int r = g + 4 * k;
            const float4 v = *reinterpret_cast<const float4*>(&panel[r * PSTRIDE + c4]);
            top4(v.x, ca.x, cb.x, cc.x, cd.x);
            top4(v.y, ca.y, cb.y, cc.y, cd.y);
            top4(v.z, ca.z, cb.z, cc.z, cd.z);
            top4(v.w, ca.w, cb.w, cc.w, cd.w);
        }

        // ---- row partial: warp w = cols [32w,32w+32), lane l = panel row l ----
        {
            float ra = -FLT_MAX, rb = -FLT_MAX, rc = -FLT_MAX, rd = -FLT_MAX;
            #pragma unroll
            for (int j = 0; j < 8; j++) {
                const float4 v = *reinterpret_cast<const float4*>(
                    &panel[l * PSTRIDE + 32 * w + 4 * j]);
                top4(v.x, ra, rb, rc, rd);
                top4(v.y, ra, rb, rc, rd);
                top4(v.z, ra, rb, rc, rd);
                top4(v.w, ra, rb, rc, rd);
            }
            rpart[w][l][0] = ra; rpart[w][l][1] = rb;
            rpart[w][l][2] = rc; rpart[w][l][3] = rd;
        }
        __syncthreads();

        // ---- finalize row 32q+t (threads 0..31); no panel access here ----
        if (t < 32) {
            float a = -FLT_MAX, b = -FLT_MAX, c = -FLT_MAX, d = -FLT_MAX;
            #pragma unroll
            for (int ww = 0; ww < 8; ww++) {
                top4(rpart[ww][t][0], a, b, c, d);
                top4(rpart[ww][t][1], a, b, c, d);
                top4(rpart[ww][t][2], a, b, c, d);
                top4(rpart[ww][t][3], a, b, c, d);
            }
            const int row = 32 * q + t;
            rthr[row]  = c;
            const bool f = (c == d);               // boundary tie
            rflag[row] = f ? 1 : 0;
            if (f) {                                // rare exact path (L2-hot row)
                float A=-FLT_MAX,B=-FLT_MAX,C=-FLT_MAX; int ia=-1,ib=-1,ic=-1;
                for (int s = 0; s < SS; s++)
                    ins3i(base[(size_t)row * SS + s], s, A, ia, B, ib, C, ic);
                ridx[row][0]=ia; ridx[row][1]=ib; ridx[row][2]=ic;
            }
        }
        // next iteration's cp.async overwrites panel; all panel reads finished
        // before the sync above, and the merge touches only rpart/rthr. safe.
    }

    // ---- column merge: 4 partial sets per column, via reused panel scratch ----
    {
        float* cpm = panel;                         // 4 groups x 64 quads x 16 floats
        const int bi = (g * 64 + (t & 63)) * 16;
        cpm[bi+ 0]=ca.x; cpm[bi+ 1]=cb.x; cpm[bi+ 2]=cc.x; cpm[bi+ 3]=cd.x;
        cpm[bi+ 4]=ca.y; cpm[bi+ 5]=cb.y; cpm[bi+ 6]=cc.y; cpm[bi+ 7]=cd.y;
        cpm[bi+ 8]=ca.z; cpm[bi+ 9]=cb.z; cpm[bi+10]=cc.z; cpm[bi+11]=cd.z;
        cpm[bi+12]=ca.w; cpm[bi+13]=cb.w; cpm[bi+14]=cc.w; cpm[bi+15]=cd.w;
    }
    __syncthreads();
    {
        const float* cpm = panel;
        const int cq = t >> 2, comp = t & 3;        // thread t owns column t
        float a = -FLT_MAX, b = -FLT_MAX, c = -FLT_MAX, d = -FLT_MAX;
        #pragma unroll
        for (int gg = 0; gg < 4; gg++) {
            const float* qv = &cpm[(gg * 64 + cq) * 16 + comp * 4];
            top4(qv[0], a, b, c, d); top4(qv[1], a, b, c, d);
            top4(qv[2], a, b, c, d); top4(qv[3], a, b, c, d);
        }
        cthr[t] = c;
        const bool f = (c == d);
        cflag[t] = f ? 1 : 0;
        if (f) {                                     // rare exact path
            float A=-FLT_MAX,B=-FLT_MAX,C=-FLT_MAX; int ia=-1,ib=-1,ic=-1;
            for (int r = 0; r < RR; r++)
                ins3i(base[(size_t)r * SS + t], r, A, ia, B, ib, C, ic);
            cidx[t][0]=ia; cidx[t][1]=ib; cidx[t][2]=ic;
        }
    }
    __syncthreads();

    // ======================= PASS B: emit ==================================
    {
        const int s0 = c4;
        const float4 cth4 = make_float4(cthr[s0], cthr[s0+1], cthr[s0+2], cthr[s0+3]);
        const uint32_t cflags =
            (uint32_t)cflag[s0]
          | ((uint32_t)cflag[s0+1] << 1)
          | ((uint32_t)cflag[s0+2] << 2)
          | ((uint32_t)cflag[s0+3] << 3);
        const int4 sm4 = *reinterpret_cast<const int4*>(&srcm[p * SS + s0]);
        const bool sm0 = sm4.x != 0, sm1 = sm4.y != 0, sm2 = sm4.z != 0, sm3 = sm4.w != 0;

        int ci[4][3];
        if (cflags) {
            #pragma unroll
            for (int k = 0; k < 4; k++) {
                if ((cflags >> k) & 1) {
                    ci[k][0] = cidx[s0+k][0]; ci[k][1] = cidx[s0+k][1]; ci[k][2] = cidx[s0+k][2];
                } else { ci[k][0] = ci[k][1] = ci[k][2] = -9; }
            }
        }

        float* outs = out + (size_t)p * (RR * SS);
        float* outc = out + (size_t)n_total + (size_t)p * (RR * SS);

        // descending rows: most-recently-loaded panels first (L2 recency)
        #pragma unroll 4
        for (int j = 63; j >= 0; j--) {
            const int r = 4 * j + g;
            const float rthr_r = rthr[r];
            const bool  rm     = rmask_sh[r] != 0;
            const size_t off   = (size_t)r * SS + s0;
            const float4 v4 = *reinterpret_cast<const float4*>(base + off);

            bool fr0, fr1, fr2, fr3;
            if (!rflag[r]) {                          // warp-uniform branch
                fr0 = v4.x >= rthr_r; fr1 = v4.y >= rthr_r;
                fr2 = v4.z >= rthr_r; fr3 = v4.w >= rthr_r;
            } else {
                const int i0 = ridx[r][0], i1 = ridx[r][1], i2 = ridx[r][2];
                fr0 = (s0+0==i0)|(s0+0==i1)|(s0+0==i2);
                fr1 = (s0+1==i0)|(s0+1==i1)|(s0+1==i2);
                fr2 = (s0+2==i0)|(s0+2==i1)|(s0+2==i2);
                fr3 = (s0+3==i0)|(s0+3==i1)|(s0+3==i2);
            }

            bool fc0 = v4.x >= cth4.x, fc1 = v4.y >= cth4.y,
                 fc2 = v4.z >= cth4.z, fc3 = v4.w >= cth4.w;
            if (cflags) {                             // rare
                if (cflags & 1) fc0 = (r==ci[0][0])|(r==ci[0][1])|(r==ci[0][2]);
                if (cflags & 2) fc1 = (r==ci[1][0])|(r==ci[1][1])|(r==ci[1][2]);
                if (cflags & 4) fc2 = (r==ci[2][0])|(r==ci[2][1])|(r==ci[2][2]);
                if (cflags & 8) fc3 = (r==ci[3][0])|(r==ci[3][1])|(r==ci[3][2]);
            }

            float4 so, co;
            {
                float e;
                e = __expf(v4.x); so.x = 0.5f*((fr0?e:0.f)+(fc0?e:0.f)); co.x = ((fr0|fc0)&&rm&&sm0)?1.f:0.f;
                e = __expf(v4.y); so.y = 0.5f*((fr1?e:0.f)+(fc1?e:0.f)); co.y = ((fr1|fc1)&&rm&&sm1)?1.f:0.f;
                e = __expf(v4.z); so.z = 0.5f*((fr2?e:0.f)+(fc2?e:0.f)); co.z = ((fr2|fc2)&&rm&&sm2)?1.f:0.f;
                e = __expf(v4.w); so.w = 0.5f*((fr3?e:0.f)+(fc3?e:0.f)); co.w = ((fr3|fc3)&&rm&&sm3)?1.f:0.f;
            }

            __stcs(reinterpret_cast<float4*>(outs + off), so);   // evict-first
            __stcs(reinterpret_cast<float4*>(outc + off), co);
        }
    }
}

extern "C" void kernel_launch(void* const* d_in, const int* in_sizes, int n_in,
                              void* d_out, int out_size) {
    const float* score = (const float*)d_in[0];
    // d_in[1] = node_corr_scores (unused: conditional=False in reference)
    const int*   refm  = (const int*)d_in[2];   // bool -> int32 in harness
    const int*   srcm  = (const int*)d_in[3];
    float* out = (float*)d_out;

    const long long n_total = (long long)in_sizes[0];   // P*R*S
    const int P = (int)(n_total / (RR * SS));

    iapm_fused<<<P, 256>>>(score, refm, srcm, out, n_total);
}

// round 12
// speedup vs baseline: 1.3990x; 1.3387x over previous
#include <cuda_runtime.h>
#include <cstdint>
#include <float.h>

// Problem shape (fixed by the dataset): P=512, R=256, S=256
#define RR 256
#define SS 256
#define MAXP 512
#define PSTRIDE 260   // panel row stride (floats): 16B-aligned, .128 LDS at conflict floor

// ---- K1 -> K2 scratch (column thresholds; idx only read when flag set) ----
__device__ float   g_cthr[MAXP * SS];
__device__ uint8_t g_cflag[MAXP * SS];
__device__ int     g_cidx[MAXP * SS * 3];

// Predicate-free top-4 value tracker: 7 FMNMX.
__device__ __forceinline__ void top4(float v, float& a, float& b, float& c, float& d) {
    float t1 = fminf(a, v);  a = fmaxf(a, v);
    float t2 = fminf(b, t1); b = fmaxf(b, t1);
    float t3 = fminf(c, t2); c = fmaxf(c, t2);
    d = fmaxf(d, t3);
}

// Stable top-3 insert with index (rare tie path): strict '>' + increasing scan
// order reproduces jax.lax.top_k tie-breaking exactly.
__device__ __forceinline__ void ins3i(float v, int i,
                                      float& a, int& ia,
                                      float& b, int& ib,
                                      float& c, int& ic) {
    bool ga = v > a, gb = v > b, gc = v > c;
    c  = gb ? b  : (gc ? v : c);
    ic = gb ? ib : (gc ? i : ic);
    b  = ga ? a  : (gb ? v : b);
    ib = ga ? ia : (gb ? i : ib);
    a  = ga ? v : a;
    ia = ga ? i : ia;
}

// ============ K1: column top-4 thresholds only (coalesced, no transpose) ====
__global__ __launch_bounds__(256, 4)
void k1_cols(const float* __restrict__ score)
{
    __shared__ float scr[4 * 64 * 16];          // 16 KB merge scratch
    const int p  = blockIdx.x;
    const int t  = threadIdx.x;
    const int g  = t >> 6;                      // row-phase group 0..3
    const int c4 = (t & 63) * 4;                // this thread's 4 columns
    const float* base = score + (size_t)p * (RR * SS);

    float4 A, B, C, D;
    A = B = C = D = make_float4(-FLT_MAX, -FLT_MAX, -FLT_MAX, -FLT_MAX);

    #pragma unroll 4
    for (int k = 0; k < 64; k++) {              // rows g, g+4, ..., g+252
        const int r = g + 4 * k;
        const float4 v = *reinterpret_cast<const float4*>(base + (size_t)r * SS + c4);
        top4(v.x, A.x, B.x, C.x, D.x);
        top4(v.y, A.y, B.y, C.y, D.y);
        top4(v.z, A.z, B.z, C.z, D.z);
        top4(v.w, A.w, B.w, C.w, D.w);
    }

    // publish partials: [group][colquad][comp*4 + rank]
    {
        const int bi = (g * 64 + (t & 63)) * 16;
        scr[bi+ 0]=A.x; scr[bi+ 1]=B.x; scr[bi+ 2]=C.x; scr[bi+ 3]=D.x;
        scr[bi+ 4]=A.y; scr[bi+ 5]=B.y; scr[bi+ 6]=C.y; scr[bi+ 7]=D.y;
        scr[bi+ 8]=A.z; scr[bi+ 9]=B.z; scr[bi+10]=C.z; scr[bi+11]=D.z;
        scr[bi+12]=A.w; scr[bi+13]=B.w; scr[bi+14]=C.w; scr[bi+15]=D.w;
    }
    __syncthreads();

    // thread t owns column t: merge the 4 group-partials
    {
        const int cq = t >> 2, comp = t & 3;
        float a = -FLT_MAX, b = -FLT_MAX, c = -FLT_MAX, d = -FLT_MAX;
        #pragma unroll
        for (int gg = 0; gg < 4; gg++) {
            const float* qv = &scr[(gg * 64 + cq) * 16 + comp * 4];
            top4(qv[0], a, b, c, d); top4(qv[1], a, b, c, d);
            top4(qv[2], a, b, c, d); top4(qv[3], a, b, c, d);
        }
        const int gi = p * SS + t;
        g_cthr[gi]  = c;
        const bool f = (c == d);                 // boundary tie
        g_cflag[gi] = f ? 1 : 0;
        if (f) {                                  // rare exact path (slice L2-hot)
            float X=-FLT_MAX,Y=-FLT_MAX,Z=-FLT_MAX; int ia=-1,ib=-1,ic=-1;
            for (int r = 0; r < RR; r++)
                ins3i(base[(size_t)r * SS + t], r, X, ia, Y, ib, Z, ic);
            g_cidx[gi*3+0]=ia; g_cidx[gi*3+1]=ib; g_cidx[gi*3+2]=ic;
        }
    }
}

// ============ K2: row top-4 from SMEM panel + emit (single gmem read) =======
// grid = P*8 ; block b -> slice p = P-1-(b>>3) (reverse: L2 reuse of K1 reads),
// panel q = b&7 covering rows [32q, 32q+32).
__global__ __launch_bounds__(256)
void k2_rows_emit(const float* __restrict__ score,
                  const int* __restrict__ refm,
                  const int* __restrict__ srcm,
                  float* __restrict__ out,
                  long long n_total, int P)
{
    __shared__ float   panel[32 * PSTRIDE];     // 33,280 B
    __shared__ float   rpart[8][32][4];         //  4,096 B
    __shared__ float   rthr_sh[32];
    __shared__ uint8_t rflag_sh[32];
    __shared__ int     ridx_sh[32][3];
    __shared__ int     rmask_sh[32];

    const int b  = blockIdx.x;
    const int p  = (P - 1) - (b >> 3);
    const int q  = b & 7;
    const int t  = threadIdx.x;
    const int w  = t >> 5;
    const int l  = t & 31;
    const int g  = t >> 6;                      // warp-uniform row phase
    const int c4 = (t & 63) * 4;
    const float* base = score + (size_t)p * (RR * SS) + (size_t)q * 32 * SS;

    // async panel load: thread loads rows g+4k (8 x 16B)
    #pragma unroll
    for (int k = 0; k < 8; k++) {
        const int r = g + 4 * k;
        uint32_t sa = (uint32_t)__cvta_generic_to_shared(&panel[r * PSTRIDE + c4]);
        const float* ga = base + (size_t)r * SS + c4;
        asm volatile("cp.async.cg.shared.global [%0], [%1], 16;" :: "r"(sa), "l"(ga));
    }
    asm volatile("cp.async.commit_group;");
    if (t < 32) rmask_sh[t] = refm[p * RR + q * 32 + t];
    asm volatile("cp.async.wait_group 0;" ::: "memory");
    __syncthreads();

    // row partials: warp w = cols [32w,32w+32), lane l = panel row l
    {
        float ra = -FLT_MAX, rb = -FLT_MAX, rc = -FLT_MAX, rd = -FLT_MAX;
        #pragma unroll
        for (int j = 0; j < 8; j++) {
            const float4 v = *reinterpret_cast<const float4*>(
                &panel[l * PSTRIDE + 32 * w + 4 * j]);
            top4(v.x, ra, rb, rc, rd);
            top4(v.y, ra, rb, rc, rd);
            top4(v.z, ra, rb, rc, rd);
            top4(v.w, ra, rb, rc, rd);
        }
        rpart[w][l][0] = ra; rpart[w][l][1] = rb;
        rpart[w][l][2] = rc; rpart[w][l][3] = rd;
    }
    __syncthreads();

    // finalize panel row t (threads 0..31)
    if (t < 32) {
        float a = -FLT_MAX, bb = -FLT_MAX, c = -FLT_MAX, d = -FLT_MAX;
        #pragma unroll
        for (int ww = 0; ww < 8; ww++) {
            top4(rpart[ww][t][0], a, bb, c, d);
            top4(rpart[ww][t][1], a, bb, c, d);
            top4(rpart[ww][t][2], a, bb, c, d);
            top4(rpart[ww][t][3], a, bb, c, d);
        }
        rthr_sh[t] = c;
        const bool f = (c == d);
        rflag_sh[t] = f ? 1 : 0;
        if (f) {                                  // rare exact path from SMEM
            float X=-FLT_MAX,Y=-FLT_MAX,Z=-FLT_MAX; int ia=-1,ib=-1,ic=-1;
            for (int s = 0; s < SS; s++)
                ins3i(panel[t * PSTRIDE + s], s, X, ia, Y, ib, Z, ic);
            ridx_sh[t][0]=ia; ridx_sh[t][1]=ib; ridx_sh[t][2]=ic;
        }
    }
    __syncthreads();

    // ---- emit from SMEM ----
    {
        const int s0 = c4;
        const int gi = p * SS + s0;
        const float4 cth4 = *reinterpret_cast<const float4*>(&g_cthr[gi]);
        const uchar4 cf4  = *reinterpret_cast<const uchar4*>(&g_cflag[gi]);
        const uint32_t cflags =
            (uint32_t)(cf4.x != 0) | ((uint32_t)(cf4.y != 0) << 1)
          | ((uint32_t)(cf4.z != 0) << 2) | ((uint32_t)(cf4.w != 0) << 3);
        const int4 sm4 = *reinterpret_cast<const int4*>(&srcm[p * SS + s0]);
        const bool sm0 = sm4.x != 0, sm1 = sm4.y != 0, sm2 = sm4.z != 0, sm3 = sm4.w != 0;

        int ci[4][3];
        if (cflags) {
            #pragma unroll
            for (int k = 0; k < 4; k++) {
                if ((cflags >> k) & 1) {
                    ci[k][0] = g_cidx[(gi+k)*3+0];
                    ci[k][1] = g_cidx[(gi+k)*3+1];
                    ci[k][2] = g_cidx[(gi+k)*3+2];
                } else { ci[k][0] = ci[k][1] = ci[k][2] = -9; }
            }
        }

        float* outs = out + (size_t)p * (RR * SS) + (size_t)q * 32 * SS;
        float* outc = outs + (size_t)n_total;

        #pragma unroll
        for (int k = 0; k < 8; k++) {
            const int rl = g + 4 * k;             // panel row (warp-uniform)
            const int rg = q * 32 + rl;           // global row in slice
            const float rthr = rthr_sh[rl];
            const bool  rm   = rmask_sh[rl] != 0;
            const float4 v4 = *reinterpret_cast<const float4*>(&panel[rl * PSTRIDE + c4]);

            bool fr0, fr1, fr2, fr3;
            if (!rflag_sh[rl]) {                  // warp-uniform branch
                fr0 = v4.x >= rthr; fr1 = v4.y >= rthr;
                fr2 = v4.z >= rthr; fr3 = v4.w >= rthr;
            } else {
                const int i0 = ridx_sh[rl][0], i1 = ridx_sh[rl][1], i2 = ridx_sh[rl][2];
                fr0 = (s0+0==i0)|(s0+0==i1)|(s0+0==i2);
                fr1 = (s0+1==i0)|(s0+1==i1)|(s0+1==i2);
                fr2 = (s0+2==i0)|(s0+2==i1)|(s0+2==i2);
                fr3 = (s0+3==i0)|(s0+3==i1)|(s0+3==i2);
            }

            bool fc0 = v4.x >= cth4.x, fc1 = v4.y >= cth4.y,
                 fc2 = v4.z >= cth4.z, fc3 = v4.w >= cth4.w;
            if (cflags) {                         // rare
                if (cflags & 1) fc0 = (rg==ci[0][0])|(rg==ci[0][1])|(rg==ci[0][2]);
                if (cflags & 2) fc1 = (rg==ci[1][0])|(rg==ci[1][1])|(rg==ci[1][2]);
                if (cflags & 4) fc2 = (rg==ci[2][0])|(rg==ci[2][1])|(rg==ci[2][2]);
                if (cflags & 8) fc3 = (rg==ci[3][0])|(rg==ci[3][1])|(rg==ci[3][2]);
            }

            float4 so, co;
            {
                float e;
                e = __expf(v4.x); so.x = 0.5f*((fr0?e:0.f)+(fc0?e:0.f)); co.x = ((fr0|fc0)&&rm&&sm0)?1.f:0.f;
                e = __expf(v4.y); so.y = 0.5f*((fr1?e:0.f)+(fc1?e:0.f)); co.y = ((fr1|fc1)&&rm&&sm1)?1.f:0.f;
                e = __expf(v4.z); so.z = 0.5f*((fr2?e:0.f)+(fc2?e:0.f)); co.z = ((fr2|fc2)&&rm&&sm2)?1.f:0.f;
                e = __expf(v4.w); so.w = 0.5f*((fr3?e:0.f)+(fc3?e:0.f)); co.w = ((fr3|fc3)&&rm&&sm3)?1.f:0.f;
            }

            const size_t off = (size_t)rl * SS + c4;
            __stcs(reinterpret_cast<float4*>(outs + off), so);   // evict-first
            __stcs(reinterpret_cast<float4*>(outc + off), co);
        }
    }
}

extern "C" void kernel_launch(void* const* d_in, const int* in_sizes, int n_in,
                              void* d_out, int out_size) {
    const float* score = (const float*)d_in[0];
    // d_in[1] = node_corr_scores (unused: conditional=False in reference)
    const int*   refm  = (const int*)d_in[2];   // bool -> int32 in harness
    const int*   srcm  = (const int*)d_in[3];
    float* out = (float*)d_out;

    const long long n_total = (long long)in_sizes[0];   // P*R*S
    const int P = (int)(n_total / (RR * SS));

    k1_cols<<<P, 256>>>(score);
    k2_rows_emit<<<P * 8, 256>>>(score, refm, srcm, out, n_total, P);
}